// round 3
// baseline (speedup 1.0000x reference)
#include <cuda_runtime.h>

#define N_ROWS 1024
#define M_ROWS 1024
#define DIM    512
#define BT     64     // output tile edge
#define KC     32     // k chunk
#define PADK   36     // row stride in smem floats: mult of 4 (align), ≡4 mod 32 (banks)

__device__ float g_zn[N_ROWS];     // ||z_n||^2
__device__ float g_zprn[M_ROWS];   // ||zpr_m||^2
__device__ float g_zs[N_ROWS];     // sum z_n
__device__ float g_zprs[M_ROWS];   // sum zpr_m

// packed f32x2 fma: acc.lo += a.lo*b.lo ; acc.hi += a.hi*b.hi
#define FMA2(acc, a, b) \
    asm volatile("fma.rn.f32x2 %0, %1, %2, %0;" : "+l"(acc) : "l"(a), "l"(b))

__device__ __forceinline__ unsigned long long pk(float x, float y) {
    unsigned long long r;
    asm("mov.b64 %0, {%1, %2};" : "=l"(r) : "f"(x), "f"(y));
    return r;
}
__device__ __forceinline__ void upk(float& x, float& y, unsigned long long v) {
    asm("mov.b64 {%0, %1}, %2;" : "=f"(x), "=f"(y) : "l"(v));
}

// One warp per row: sum and squared-norm.
__global__ void norms_kernel(const float* __restrict__ z, const float* __restrict__ zpr) {
    int warp = (blockIdx.x * blockDim.x + threadIdx.x) >> 5;
    int lane = threadIdx.x & 31;
    if (warp >= N_ROWS + M_ROWS) return;
    const float* src = (warp < N_ROWS) ? (z + (size_t)warp * DIM)
                                       : (zpr + (size_t)(warp - N_ROWS) * DIM);
    float s = 0.0f, q = 0.0f;
    #pragma unroll
    for (int i = 0; i < DIM / 32; ++i) {
        float v = src[i * 32 + lane];
        s += v;
        q = fmaf(v, v, q);
    }
    #pragma unroll
    for (int o = 16; o; o >>= 1) {
        s += __shfl_xor_sync(0xffffffffu, s, o);
        q += __shfl_xor_sync(0xffffffffu, q, o);
    }
    if (lane == 0) {
        if (warp < N_ROWS) { g_zn[warp] = q; g_zs[warp] = s; }
        else               { g_zprn[warp - N_ROWS] = q; g_zprs[warp - N_ROWS] = s; }
    }
}

// For each (n, m): l1 = 2*sum_k max(a,b) - Sa - Sb ; dp = a.b (packed FFMA2)
// l2 = sqrt(|a|^2 + |b|^2 - 2 dp).  out[m][n][3] = {l1, l2, dp}
__global__ __launch_bounds__(256, 2)
void pair_kernel(const float* __restrict__ z,
                 const float* __restrict__ zpr,
                 float* __restrict__ out) {
    __shared__ float as[BT][PADK];   // z   tile, row-major over k chunk
    __shared__ float bs[BT][PADK];   // zpr tile

    const int tid = threadIdx.x;
    const int tx = tid & 15;    // n direction, 4 rows each
    const int ty = tid >> 4;    // m direction, 4 rows each
    const int n0 = blockIdx.x * BT;
    const int m0 = blockIdx.y * BT;

    // staging: 256 threads load 64 rows x 32 k as float4 (2 per thread)
    const int scol = (tid & 7) * 4;   // k offset (float4)
    const int srow = tid >> 3;        // 0..31

    unsigned long long dp2[4][4];     // packed fp32 pair accumulators
    float lm[4][4];                   // sum of max(a,b)
    #pragma unroll
    for (int i = 0; i < 4; ++i)
        #pragma unroll
        for (int j = 0; j < 4; ++j) { dp2[i][j] = 0ull; lm[i][j] = 0.0f; }

    for (int k0 = 0; k0 < DIM; k0 += KC) {
        #pragma unroll
        for (int r = 0; r < 2; ++r) {
            int row = srow + r * 32;
            *(float4*)&as[row][scol] = *(const float4*)&z  [(size_t)(n0 + row) * DIM + k0 + scol];
            *(float4*)&bs[row][scol] = *(const float4*)&zpr[(size_t)(m0 + row) * DIM + k0 + scol];
        }
        __syncthreads();

        #pragma unroll
        for (int kk = 0; kk < KC; kk += 4) {
            float4 a4[4], b4[4];
            #pragma unroll
            for (int i = 0; i < 4; ++i) a4[i] = *(const float4*)&as[tx * 4 + i][kk];
            #pragma unroll
            for (int j = 0; j < 4; ++j) b4[j] = *(const float4*)&bs[ty * 4 + j][kk];

            #pragma unroll
            for (int i = 0; i < 4; ++i) {
                unsigned long long alo = pk(a4[i].x, a4[i].y);
                unsigned long long ahi = pk(a4[i].z, a4[i].w);
                #pragma unroll
                for (int j = 0; j < 4; ++j) {
                    FMA2(dp2[i][j], alo, pk(b4[j].x, b4[j].y));
                    FMA2(dp2[i][j], ahi, pk(b4[j].z, b4[j].w));
                    lm[i][j] += fmaxf(a4[i].x, b4[j].x);
                    lm[i][j] += fmaxf(a4[i].y, b4[j].y);
                    lm[i][j] += fmaxf(a4[i].z, b4[j].z);
                    lm[i][j] += fmaxf(a4[i].w, b4[j].w);
                }
            }
        }
        __syncthreads();
    }

    // epilogue
    float zn[4], zs[4], pn[4], ps[4];
    #pragma unroll
    for (int i = 0; i < 4; ++i) { zn[i] = g_zn[n0 + tx * 4 + i]; zs[i] = g_zs[n0 + tx * 4 + i]; }
    #pragma unroll
    for (int j = 0; j < 4; ++j) { pn[j] = g_zprn[m0 + ty * 4 + j]; ps[j] = g_zprs[m0 + ty * 4 + j]; }

    #pragma unroll
    for (int j = 0; j < 4; ++j) {
        #pragma unroll
        for (int i = 0; i < 4; ++i) {
            float lo, hi;
            upk(lo, hi, dp2[i][j]);
            float dp = lo + hi;
            float l1 = 2.0f * lm[i][j] - zs[i] - ps[j];
            float l2 = sqrtf(fmaxf(zn[i] + pn[j] - 2.0f * dp, 0.0f));
            int n = n0 + tx * 4 + i;
            int m = m0 + ty * 4 + j;
            float* o = out + ((size_t)m * N_ROWS + n) * 3;
            o[0] = l1;
            o[1] = l2;
            o[2] = dp;
        }
    }
}

extern "C" void kernel_launch(void* const* d_in, const int* in_sizes, int n_in,
                              void* d_out, int out_size) {
    const float* z   = (const float*)d_in[0];
    const float* zpr = (const float*)d_in[1];
    float* out = (float*)d_out;

    norms_kernel<<<(N_ROWS + M_ROWS) * 32 / 256, 256>>>(z, zpr);

    dim3 grid(N_ROWS / BT, M_ROWS / BT);
    pair_kernel<<<grid, 256>>>(z, zpr, out);
}

// round 4
// speedup vs baseline: 1.0007x; 1.0007x over previous
#include <cuda_runtime.h>

#define N_ROWS 1024
#define M_ROWS 1024
#define DIM    512
#define BT     64     // output tile edge
#define KC     32     // k chunk
#define PADK   36     // row stride in smem floats: mult of 4 (align), ≡4 mod 32 (banks)

__device__ float g_zn[N_ROWS];     // ||z_n||^2
__device__ float g_zprn[M_ROWS];   // ||zpr_m||^2
__device__ float g_zs[N_ROWS];     // sum z_n
__device__ float g_zprs[M_ROWS];   // sum zpr_m

// packed f32x2 fma: acc.lo += a.lo*b.lo ; acc.hi += a.hi*b.hi
#define FMA2(acc, a, b) \
    asm volatile("fma.rn.f32x2 %0, %1, %2, %0;" : "+l"(acc) : "l"(a), "l"(b))

__device__ __forceinline__ unsigned long long pk(float x, float y) {
    unsigned long long r;
    asm("mov.b64 %0, {%1, %2};" : "=l"(r) : "f"(x), "f"(y));
    return r;
}
__device__ __forceinline__ void upk(float& x, float& y, unsigned long long v) {
    asm("mov.b64 {%0, %1}, %2;" : "=f"(x), "=f"(y) : "l"(v));
}

// One warp per row: sum and squared-norm.
__global__ void norms_kernel(const float* __restrict__ z, const float* __restrict__ zpr) {
    int warp = (blockIdx.x * blockDim.x + threadIdx.x) >> 5;
    int lane = threadIdx.x & 31;
    if (warp >= N_ROWS + M_ROWS) return;
    const float* src = (warp < N_ROWS) ? (z + (size_t)warp * DIM)
                                       : (zpr + (size_t)(warp - N_ROWS) * DIM);
    float s = 0.0f, q = 0.0f;
    #pragma unroll
    for (int i = 0; i < DIM / 32; ++i) {
        float v = src[i * 32 + lane];
        s += v;
        q = fmaf(v, v, q);
    }
    #pragma unroll
    for (int o = 16; o; o >>= 1) {
        s += __shfl_xor_sync(0xffffffffu, s, o);
        q += __shfl_xor_sync(0xffffffffu, q, o);
    }
    if (lane == 0) {
        if (warp < N_ROWS) { g_zn[warp] = q; g_zs[warp] = s; }
        else               { g_zprn[warp - N_ROWS] = q; g_zprs[warp - N_ROWS] = s; }
    }
}

// For each (n, m): l1 = 2*sum_k max(a,b) - Sa - Sb ; dp = a.b (packed FFMA2)
// l2 = sqrt(|a|^2 + |b|^2 - 2 dp).  out[m][n][3] = {l1, l2, dp}
__global__ __launch_bounds__(256, 2)
void pair_kernel(const float* __restrict__ z,
                 const float* __restrict__ zpr,
                 float* __restrict__ out) {
    __shared__ float as[BT][PADK];   // z   tile, row-major over k chunk
    __shared__ float bs[BT][PADK];   // zpr tile

    const int tid = threadIdx.x;
    const int tx = tid & 15;    // n direction, 4 rows each
    const int ty = tid >> 4;    // m direction, 4 rows each
    const int n0 = blockIdx.x * BT;
    const int m0 = blockIdx.y * BT;

    // staging: 256 threads load 64 rows x 32 k as float4 (2 per thread)
    const int scol = (tid & 7) * 4;   // k offset (float4)
    const int srow = tid >> 3;        // 0..31

    unsigned long long dp2[4][4];     // packed fp32 pair accumulators
    float lm[4][4];                   // sum of max(a,b)
    #pragma unroll
    for (int i = 0; i < 4; ++i)
        #pragma unroll
        for (int j = 0; j < 4; ++j) { dp2[i][j] = 0ull; lm[i][j] = 0.0f; }

    for (int k0 = 0; k0 < DIM; k0 += KC) {
        #pragma unroll
        for (int r = 0; r < 2; ++r) {
            int row = srow + r * 32;
            *(float4*)&as[row][scol] = *(const float4*)&z  [(size_t)(n0 + row) * DIM + k0 + scol];
            *(float4*)&bs[row][scol] = *(const float4*)&zpr[(size_t)(m0 + row) * DIM + k0 + scol];
        }
        __syncthreads();

        #pragma unroll
        for (int kk = 0; kk < KC; kk += 4) {
            float4 a4[4], b4[4];
            #pragma unroll
            for (int i = 0; i < 4; ++i) a4[i] = *(const float4*)&as[tx * 4 + i][kk];
            #pragma unroll
            for (int j = 0; j < 4; ++j) b4[j] = *(const float4*)&bs[ty * 4 + j][kk];

            #pragma unroll
            for (int i = 0; i < 4; ++i) {
                unsigned long long alo = pk(a4[i].x, a4[i].y);
                unsigned long long ahi = pk(a4[i].z, a4[i].w);
                #pragma unroll
                for (int j = 0; j < 4; ++j) {
                    FMA2(dp2[i][j], alo, pk(b4[j].x, b4[j].y));
                    FMA2(dp2[i][j], ahi, pk(b4[j].z, b4[j].w));
                    lm[i][j] += fmaxf(a4[i].x, b4[j].x);
                    lm[i][j] += fmaxf(a4[i].y, b4[j].y);
                    lm[i][j] += fmaxf(a4[i].z, b4[j].z);
                    lm[i][j] += fmaxf(a4[i].w, b4[j].w);
                }
            }
        }
        __syncthreads();
    }

    // epilogue
    float zn[4], zs[4], pn[4], ps[4];
    #pragma unroll
    for (int i = 0; i < 4; ++i) { zn[i] = g_zn[n0 + tx * 4 + i]; zs[i] = g_zs[n0 + tx * 4 + i]; }
    #pragma unroll
    for (int j = 0; j < 4; ++j) { pn[j] = g_zprn[m0 + ty * 4 + j]; ps[j] = g_zprs[m0 + ty * 4 + j]; }

    #pragma unroll
    for (int j = 0; j < 4; ++j) {
        #pragma unroll
        for (int i = 0; i < 4; ++i) {
            float lo, hi;
            upk(lo, hi, dp2[i][j]);
            float dp = lo + hi;
            float l1 = 2.0f * lm[i][j] - zs[i] - ps[j];
            float l2 = sqrtf(fmaxf(zn[i] + pn[j] - 2.0f * dp, 0.0f));
            int n = n0 + tx * 4 + i;
            int m = m0 + ty * 4 + j;
            float* o = out + ((size_t)m * N_ROWS + n) * 3;
            o[0] = l1;
            o[1] = l2;
            o[2] = dp;
        }
    }
}

extern "C" void kernel_launch(void* const* d_in, const int* in_sizes, int n_in,
                              void* d_out, int out_size) {
    const float* z   = (const float*)d_in[0];
    const float* zpr = (const float*)d_in[1];
    float* out = (float*)d_out;

    norms_kernel<<<(N_ROWS + M_ROWS) * 32 / 256, 256>>>(z, zpr);

    dim3 grid(N_ROWS / BT, M_ROWS / BT);
    pair_kernel<<<grid, 256>>>(z, zpr, out);
}

// round 5
// speedup vs baseline: 1.0424x; 1.0417x over previous
#include <cuda_runtime.h>

#define N_ROWS 1024
#define M_ROWS 1024
#define DIM    512
#define BT     64     // output tile edge
#define KC     32     // k chunk
#define PADK   36     // smem row stride (floats): 144B ≡ 16 mod 128 → conflict-free strided rows

using u64 = unsigned long long;

__device__ float g_zn[N_ROWS];     // ||z_n||^2
__device__ float g_zprn[M_ROWS];   // ||zpr_m||^2

// packed fp32 pair ops (sm_100+)
#define FMA2(acc, a, b) asm("fma.rn.f32x2 %0, %1, %2, %0;" : "+l"(acc) : "l"(a), "l"(b))
#define ACC2(acc, x)    asm("add.rn.f32x2 %0, %0, %1;"     : "+l"(acc) : "l"(x))
#define ADD2(d, a, b)   asm("add.rn.f32x2 %0, %1, %2;"     : "=l"(d)   : "l"(a), "l"(b))

__device__ __forceinline__ void upk(float& x, float& y, u64 v) {
    asm("mov.b64 {%0, %1}, %2;" : "=f"(x), "=f"(y) : "l"(v));
}

// One warp per row: squared-norm reduction.
__global__ void norms_kernel(const float* __restrict__ z, const float* __restrict__ zpr) {
    int warp = (blockIdx.x * blockDim.x + threadIdx.x) >> 5;
    int lane = threadIdx.x & 31;
    if (warp >= N_ROWS + M_ROWS) return;
    const float* src = (warp < N_ROWS) ? (z + (size_t)warp * DIM)
                                       : (zpr + (size_t)(warp - N_ROWS) * DIM);
    float q = 0.0f;
    #pragma unroll
    for (int i = 0; i < DIM / 32; ++i) {
        float v = src[i * 32 + lane];
        q = fmaf(v, v, q);
    }
    #pragma unroll
    for (int o = 16; o; o >>= 1) q += __shfl_xor_sync(0xffffffffu, q, o);
    if (lane == 0) {
        if (warp < N_ROWS) g_zn[warp] = q;
        else               g_zprn[warp - N_ROWS] = q;
    }
}

// For each (n, m): l1 = sum |a-b| (packed), dpneg = sum a*(-b) (packed FFMA2),
// l2 = sqrt(|a|^2 + |b|^2 + 2*dpneg).  out[m][n][3] = {l1, l2, -dpneg}
__global__ __launch_bounds__(256, 2)
void pair_kernel(const float* __restrict__ z,
                 const float* __restrict__ zpr,
                 float* __restrict__ out) {
    __shared__ __align__(16) float as[BT][PADK];   // z   tile: [row][k]
    __shared__ __align__(16) float bs[BT][PADK];   // zpr tile: [row][k]

    const int tid = threadIdx.x;
    const int tx = tid & 15;    // n rows: tx + 16*i
    const int ty = tid >> 4;    // m rows: ty + 16*j
    const int n0 = blockIdx.x * BT;
    const int m0 = blockIdx.y * BT;

    // staging: 256 threads x 2 float4 = 64 rows x 32 k (coalesced, conflict-free)
    const int scol = (tid & 7) * 4;
    const int srow = tid >> 3;

    const u64 SGN = 0x8000000080000000ull;
    const u64 ABS = 0x7fffffff7fffffffull;

    u64 dpn[4][4];   // packed accumulators of a*(-b)
    u64 l1a[4][4];   // packed accumulators of |a-b|
    #pragma unroll
    for (int i = 0; i < 4; ++i)
        #pragma unroll
        for (int j = 0; j < 4; ++j) { dpn[i][j] = 0ull; l1a[i][j] = 0ull; }

    for (int k0 = 0; k0 < DIM; k0 += KC) {
        #pragma unroll
        for (int r = 0; r < 2; ++r) {
            int row = srow + r * 32;
            *(float4*)&as[row][scol] = *(const float4*)&z  [(size_t)(n0 + row) * DIM + k0 + scol];
            *(float4*)&bs[row][scol] = *(const float4*)&zpr[(size_t)(m0 + row) * DIM + k0 + scol];
        }
        __syncthreads();

        #pragma unroll
        for (int kk = 0; kk < KC; kk += 4) {
            u64 a[4][2], bn[4][2];
            #pragma unroll
            for (int i = 0; i < 4; ++i) {
                ulonglong2 t = *(const ulonglong2*)&as[tx + 16 * i][kk];  // LDS.128, packed pairs
                a[i][0] = t.x; a[i][1] = t.y;
            }
            #pragma unroll
            for (int j = 0; j < 4; ++j) {
                ulonglong2 t = *(const ulonglong2*)&bs[ty + 16 * j][kk];  // broadcast
                bn[j][0] = t.x ^ SGN;                                     // -b (2x LOP3)
                bn[j][1] = t.y ^ SGN;
            }
            #pragma unroll
            for (int i = 0; i < 4; ++i) {
                #pragma unroll
                for (int j = 0; j < 4; ++j) {
                    u64 d0, d1;
                    ADD2(d0, a[i][0], bn[j][0]);     // a - b  (packed)
                    ADD2(d1, a[i][1], bn[j][1]);
                    d0 &= ABS;                        // |.| on both halves (LOP3, alu)
                    d1 &= ABS;
                    ACC2(l1a[i][j], d0);
                    ACC2(l1a[i][j], d1);
                    FMA2(dpn[i][j], a[i][0], bn[j][0]);   // += a*(-b)
                    FMA2(dpn[i][j], a[i][1], bn[j][1]);
                }
            }
        }
        __syncthreads();
    }

    // epilogue
    float zn[4], pn[4];
    #pragma unroll
    for (int i = 0; i < 4; ++i) zn[i] = g_zn[n0 + tx + 16 * i];
    #pragma unroll
    for (int j = 0; j < 4; ++j) pn[j] = g_zprn[m0 + ty + 16 * j];

    #pragma unroll
    for (int j = 0; j < 4; ++j) {
        #pragma unroll
        for (int i = 0; i < 4; ++i) {
            float l1lo, l1hi, dlo, dhi;
            upk(l1lo, l1hi, l1a[i][j]);
            upk(dlo, dhi, dpn[i][j]);
            float dpneg = dlo + dhi;           // = -dot
            float l1 = l1lo + l1hi;
            float l2 = sqrtf(fmaxf(zn[i] + pn[j] + 2.0f * dpneg, 0.0f));
            int n = n0 + tx + 16 * i;
            int m = m0 + ty + 16 * j;
            float* o = out + ((size_t)m * N_ROWS + n) * 3;
            o[0] = l1;
            o[1] = l2;
            o[2] = -dpneg;
        }
    }
}

extern "C" void kernel_launch(void* const* d_in, const int* in_sizes, int n_in,
                              void* d_out, int out_size) {
    const float* z   = (const float*)d_in[0];
    const float* zpr = (const float*)d_in[1];
    float* out = (float*)d_out;

    norms_kernel<<<(N_ROWS + M_ROWS) * 32 / 256, 256>>>(z, zpr);

    dim3 grid(N_ROWS / BT, M_ROWS / BT);
    pair_kernel<<<grid, 256>>>(z, zpr, out);
}

// round 6
// speedup vs baseline: 1.1384x; 1.0922x over previous
#include <cuda_runtime.h>

#define N_ROWS 1024
#define M_ROWS 1024
#define DIM    512
#define BT     64    // block tile (both n and m)
#define KC     32    // k chunk
#define PAD    68    // padded row length in smem (R2-proven layout)

__device__ float g_zn[N_ROWS];     // ||z_n||^2
__device__ float g_zprn[M_ROWS];   // ||zpr_m||^2
__device__ float g_zs[N_ROWS];     // sum z_n
__device__ float g_zprs[M_ROWS];   // sum zpr_m

// One warp per row: sum + squared-norm reduction.
__global__ void norms_kernel(const float* __restrict__ z, const float* __restrict__ zpr) {
    int warp = (blockIdx.x * blockDim.x + threadIdx.x) >> 5;
    int lane = threadIdx.x & 31;
    if (warp >= N_ROWS + M_ROWS) return;
    const float* src = (warp < N_ROWS) ? (z + (size_t)warp * DIM)
                                       : (zpr + (size_t)(warp - N_ROWS) * DIM);
    float s = 0.0f, q = 0.0f;
    #pragma unroll
    for (int i = 0; i < DIM / 32; ++i) {
        float v = src[i * 32 + lane];
        s += v;
        q = fmaf(v, v, q);
    }
    #pragma unroll
    for (int o = 16; o; o >>= 1) {
        s += __shfl_xor_sync(0xffffffffu, s, o);
        q += __shfl_xor_sync(0xffffffffu, q, o);
    }
    if (lane == 0) {
        if (warp < N_ROWS) { g_zn[warp] = q; g_zs[warp] = s; }
        else               { g_zprn[warp - N_ROWS] = q; g_zprs[warp - N_ROWS] = s; }
    }
}

// Per pair: dp = a.b (FFMA, fma pipe); lm = sum max(a,b) (FMNMX alu + FADD fma);
// l1 = 2*lm - Sa - Sb; l2 = sqrt(|a|^2+|b|^2-2dp). out[m][n][3] = {l1, l2, dp}
__global__ __launch_bounds__(256, 2)
void pair_kernel(const float* __restrict__ z,
                 const float* __restrict__ zpr,
                 float* __restrict__ out) {
    __shared__ float as[KC][PAD];  // z   chunk, transposed: as[k][n_local]
    __shared__ float bs[KC][PAD];  // zpr chunk, transposed: bs[k][m_local]

    const int tid = threadIdx.x;
    const int tx = tid & 15;   // n direction (4 rows each)
    const int ty = tid >> 4;   // m direction (4 rows each)
    const int n0 = blockIdx.x * BT;
    const int m0 = blockIdx.y * BT;

    // staging: 32 consecutive lanes read 32 consecutive k (coalesced 128B)
    const int lcol = tid & 31;   // k within chunk
    const int lrow = tid >> 5;   // row base, step 8

    float lm[4][4];   // sum of max(a,b)
    float dp[4][4];
    #pragma unroll
    for (int i = 0; i < 4; ++i)
        #pragma unroll
        for (int j = 0; j < 4; ++j) { lm[i][j] = 0.0f; dp[i][j] = 0.0f; }

    for (int k0 = 0; k0 < DIM; k0 += KC) {
        #pragma unroll
        for (int r = 0; r < 8; ++r) {
            int row = lrow + r * 8;
            as[lcol][row] = z  [(size_t)(n0 + row) * DIM + k0 + lcol];
            bs[lcol][row] = zpr[(size_t)(m0 + row) * DIM + k0 + lcol];
        }
        __syncthreads();

        #pragma unroll
        for (int kk = 0; kk < KC; ++kk) {
            float4 a4 = *(const float4*)&as[kk][tx * 4];
            float4 b4 = *(const float4*)&bs[kk][ty * 4];
            float av[4] = {a4.x, a4.y, a4.z, a4.w};
            float bv[4] = {b4.x, b4.y, b4.z, b4.w};
            #pragma unroll
            for (int i = 0; i < 4; ++i) {
                #pragma unroll
                for (int j = 0; j < 4; ++j) {
                    lm[i][j] += fmaxf(av[i], bv[j]);          // FMNMX (alu) + FADD (fma)
                    dp[i][j] = fmaf(av[i], bv[j], dp[i][j]);  // FFMA (fma)
                }
            }
        }
        __syncthreads();
    }

    // epilogue
    float zn[4], zs[4], pn[4], ps[4];
    #pragma unroll
    for (int i = 0; i < 4; ++i) { zn[i] = g_zn[n0 + tx * 4 + i]; zs[i] = g_zs[n0 + tx * 4 + i]; }
    #pragma unroll
    for (int j = 0; j < 4; ++j) { pn[j] = g_zprn[m0 + ty * 4 + j]; ps[j] = g_zprs[m0 + ty * 4 + j]; }

    #pragma unroll
    for (int j = 0; j < 4; ++j) {
        #pragma unroll
        for (int i = 0; i < 4; ++i) {
            int n = n0 + tx * 4 + i;
            int m = m0 + ty * 4 + j;
            float l1 = 2.0f * lm[i][j] - zs[i] - ps[j];
            float l2sq = zn[i] + pn[j] - 2.0f * dp[i][j];
            float l2 = sqrtf(fmaxf(l2sq, 0.0f));
            float* o = out + ((size_t)m * N_ROWS + n) * 3;
            o[0] = l1;
            o[1] = l2;
            o[2] = dp[i][j];
        }
    }
}

extern "C" void kernel_launch(void* const* d_in, const int* in_sizes, int n_in,
                              void* d_out, int out_size) {
    const float* z   = (const float*)d_in[0];
    const float* zpr = (const float*)d_in[1];
    float* out = (float*)d_out;

    norms_kernel<<<(N_ROWS + M_ROWS) * 32 / 256, 256>>>(z, zpr);

    dim3 grid(N_ROWS / BT, M_ROWS / BT);
    pair_kernel<<<grid, 256>>>(z, zpr, out);
}

// round 7
// speedup vs baseline: 1.3755x; 1.2082x over previous
#include <cuda_runtime.h>
#include <cstdint>

#define N_ROWS 1024
#define M_ROWS 1024
#define DIM    512
#define BT     64
#define KC     32
#define NCH    (DIM / KC)   // 16 chunks
#define PADK   36           // row stride: 144B; stride-16 rows -> conflict-free LDS.128

using u64 = unsigned long long;

__device__ float g_zn[N_ROWS];     // ||z_n||^2
__device__ float g_zprn[M_ROWS];   // ||zpr_m||^2
__device__ float g_zs[N_ROWS];     // sum z_n
__device__ float g_zprs[M_ROWS];   // sum zpr_m

// packed fp32 fma: acc.lo += a.lo*b.lo ; acc.hi += a.hi*b.hi  (1 issue slot / 2 elems)
#define FMA2(acc, a, b) asm("fma.rn.f32x2 %0, %1, %2, %0;" : "+l"(acc) : "l"(a), "l"(b))

__device__ __forceinline__ void upk(float& x, float& y, u64 v) {
    asm("mov.b64 {%0, %1}, %2;" : "=f"(x), "=f"(y) : "l"(v));
}

__device__ __forceinline__ void cp16(uint32_t smem, const void* g) {
    asm volatile("cp.async.cg.shared.global [%0], [%1], 16;" :: "r"(smem), "l"(g));
}
#define CP_COMMIT() asm volatile("cp.async.commit_group;")
#define CP_WAIT0()  asm volatile("cp.async.wait_group 0;")

// One warp per row: sum + squared-norm.
__global__ void norms_kernel(const float* __restrict__ z, const float* __restrict__ zpr) {
    int warp = (blockIdx.x * blockDim.x + threadIdx.x) >> 5;
    int lane = threadIdx.x & 31;
    if (warp >= N_ROWS + M_ROWS) return;
    const float* src = (warp < N_ROWS) ? (z + (size_t)warp * DIM)
                                       : (zpr + (size_t)(warp - N_ROWS) * DIM);
    float s = 0.0f, q = 0.0f;
    #pragma unroll
    for (int i = 0; i < DIM / 32; ++i) {
        float v = src[i * 32 + lane];
        s += v;
        q = fmaf(v, v, q);
    }
    #pragma unroll
    for (int o = 16; o; o >>= 1) {
        s += __shfl_xor_sync(0xffffffffu, s, o);
        q += __shfl_xor_sync(0xffffffffu, q, o);
    }
    if (lane == 0) {
        if (warp < N_ROWS) { g_zn[warp] = q; g_zs[warp] = s; }
        else               { g_zprn[warp - N_ROWS] = q; g_zprs[warp - N_ROWS] = s; }
    }
}

// dp via packed FFMA2; L1 via 2*sum max(a,b) - Sa - Sb (FMNMX alu + FADD fma).
// out[m][n][3] = {l1, l2, dp}
__global__ __launch_bounds__(256, 2)
void pair_kernel(const float* __restrict__ z,
                 const float* __restrict__ zpr,
                 float* __restrict__ out) {
    __shared__ __align__(16) float as[2][BT][PADK];   // z   tiles, row-major [row][k]
    __shared__ __align__(16) float bs[2][BT][PADK];   // zpr tiles

    const int tid = threadIdx.x;
    const int tx = tid & 15;    // n rows: tx + 16*i
    const int ty = tid >> 4;    // m rows: ty + 16*j
    const int n0 = blockIdx.x * BT;
    const int m0 = blockIdx.y * BT;

    // staging: each thread cp.asyncs 4x16B per chunk (rows tid>>3 and +32, col (tid&7)*4)
    const int scol = (tid & 7) * 4;
    const int srow = tid >> 3;
    const float* gz  = z   + (size_t)(n0 + srow) * DIM + scol;
    const float* gzp = zpr + (size_t)(m0 + srow) * DIM + scol;

    uint32_t sa0 = (uint32_t)__cvta_generic_to_shared(&as[0][srow][scol]);
    uint32_t sa1 = (uint32_t)__cvta_generic_to_shared(&as[0][srow + 32][scol]);
    uint32_t sb0 = (uint32_t)__cvta_generic_to_shared(&bs[0][srow][scol]);
    uint32_t sb1 = (uint32_t)__cvta_generic_to_shared(&bs[0][srow + 32][scol]);
    const uint32_t BUFOFF = (uint32_t)(BT * PADK * sizeof(float));

    u64  dpn[4][4];   // packed dot accumulators (even-k, odd-k)
    float lm[4][4];   // sum of max(a,b)
    #pragma unroll
    for (int i = 0; i < 4; ++i)
        #pragma unroll
        for (int j = 0; j < 4; ++j) { dpn[i][j] = 0ull; lm[i][j] = 0.0f; }

    // prefetch chunk 0 into buffer 0
    cp16(sa0, gz);            cp16(sa1, gz  + (size_t)32 * DIM);
    cp16(sb0, gzp);           cp16(sb1, gzp + (size_t)32 * DIM);
    CP_COMMIT();

    for (int c = 0; c < NCH; ++c) {
        CP_WAIT0();
        __syncthreads();      // chunk c resident & visible; compute(c-1) done for all

        if (c + 1 < NCH) {    // stage chunk c+1 into the other buffer
            uint32_t o = ((c + 1) & 1) * BUFOFF;
            const float* pz  = gz  + (c + 1) * KC;
            const float* pzp = gzp + (c + 1) * KC;
            cp16(sa0 + o, pz);   cp16(sa1 + o, pz  + (size_t)32 * DIM);
            cp16(sb0 + o, pzp);  cp16(sb1 + o, pzp + (size_t)32 * DIM);
            CP_COMMIT();
        }

        const int s = c & 1;
        #pragma unroll
        for (int kk = 0; kk < KC; kk += 4) {
            u64 a[4][2], b[4][2];
            float af[4][4], bf[4][4];
            #pragma unroll
            for (int i = 0; i < 4; ++i) {
                ulonglong2 t = *(const ulonglong2*)&as[s][tx + 16 * i][kk];  // LDS.128
                a[i][0] = t.x; a[i][1] = t.y;
                upk(af[i][0], af[i][1], t.x);
                upk(af[i][2], af[i][3], t.y);
            }
            #pragma unroll
            for (int j = 0; j < 4; ++j) {
                ulonglong2 t = *(const ulonglong2*)&bs[s][ty + 16 * j][kk];  // broadcast
                b[j][0] = t.x; b[j][1] = t.y;
                upk(bf[j][0], bf[j][1], t.x);
                upk(bf[j][2], bf[j][3], t.y);
            }
            #pragma unroll
            for (int i = 0; i < 4; ++i) {
                #pragma unroll
                for (int j = 0; j < 4; ++j) {
                    FMA2(dpn[i][j], a[i][0], b[j][0]);        // 2 elems / issue
                    FMA2(dpn[i][j], a[i][1], b[j][1]);
                    lm[i][j] += fmaxf(af[i][0], bf[j][0]);    // FMNMX(alu)+FADD(fma)
                    lm[i][j] += fmaxf(af[i][1], bf[j][1]);
                    lm[i][j] += fmaxf(af[i][2], bf[j][2]);
                    lm[i][j] += fmaxf(af[i][3], bf[j][3]);
                }
            }
        }
        __syncthreads();      // compute(c) done before buffer s is restaged in c+2
    }

    // epilogue
    float zn[4], zs[4], pn[4], ps[4];
    #pragma unroll
    for (int i = 0; i < 4; ++i) { zn[i] = g_zn[n0 + tx + 16 * i]; zs[i] = g_zs[n0 + tx + 16 * i]; }
    #pragma unroll
    for (int j = 0; j < 4; ++j) { pn[j] = g_zprn[m0 + ty + 16 * j]; ps[j] = g_zprs[m0 + ty + 16 * j]; }

    #pragma unroll
    for (int j = 0; j < 4; ++j) {
        #pragma unroll
        for (int i = 0; i < 4; ++i) {
            float dlo, dhi;
            upk(dlo, dhi, dpn[i][j]);
            float dp = dlo + dhi;
            float l1 = 2.0f * lm[i][j] - zs[i] - ps[j];
            float l2 = sqrtf(fmaxf(zn[i] + pn[j] - 2.0f * dp, 0.0f));
            int n = n0 + tx + 16 * i;
            int m = m0 + ty + 16 * j;
            float* o = out + ((size_t)m * N_ROWS + n) * 3;
            o[0] = l1;
            o[1] = l2;
            o[2] = dp;
        }
    }
}

extern "C" void kernel_launch(void* const* d_in, const int* in_sizes, int n_in,
                              void* d_out, int out_size) {
    const float* z   = (const float*)d_in[0];
    const float* zpr = (const float*)d_in[1];
    float* out = (float*)d_out;

    norms_kernel<<<(N_ROWS + M_ROWS) * 32 / 256, 256>>>(z, zpr);

    dim3 grid(N_ROWS / BT, M_ROWS / BT);
    pair_kernel<<<grid, 256>>>(z, zpr, out);
}